// round 16
// baseline (speedup 1.0000x reference)
#include <cuda_runtime.h>
#include <cuda_fp16.h>
#include <math.h>
#include <limits.h>

#define NMAX 50000
#define EMAX 800000
#define HCMAX 256

// ---------------- scratch ----------------
__device__ __half g_hbuf[NMAX * HCMAX];
__device__ __half g_aggbuf[NMAX * HCMAX];
__device__ __half g_xh[NMAX * 128];
__device__ __half g_w1h[128 * 256];
__device__ __half g_w2h[256 * 256];
__device__ float g_h3[NMAX * 2];
__device__ float g_as[NMAX * 4];
__device__ float g_ad[NMAX * 4];
__device__ float g_as3[NMAX];
__device__ float g_ad3[NMAX];
__device__ int   g_deg[NMAX];
__device__ int   g_offs[NMAX];
__device__ int   g_cursor[NMAX];
__device__ int   g_bsum[256];
__device__ int   g_csr_src[EMAX];

static inline int cdiv(int a, int b) { return (a + b - 1) / b; }

// ---------------- fp32 -> fp16 convert ----------------
__global__ void f32_to_f16_kernel(const float* __restrict__ in, __half* __restrict__ out, int n4) {
    int i = blockIdx.x * blockDim.x + threadIdx.x;
    if (i >= n4) return;
    float4 v = ((const float4*)in)[i];
    ((__half2*)out)[i * 2] = __floats2half2_rn(v.x, v.y);
    ((__half2*)out)[i * 2 + 1] = __floats2half2_rn(v.z, v.w);
}

// ---------------- utility ----------------
__global__ void fill_i32(int* p, int v, int n) {
    int i = blockIdx.x * blockDim.x + threadIdx.x;
    if (i < n) p[i] = v;
}

// ---------------- CSR build ----------------
__global__ void hist_kernel(const int* __restrict__ ei, int* __restrict__ deg, int E) {
    int i = blockIdx.x * blockDim.x + threadIdx.x;
    if (i < E) atomicAdd(&deg[ei[E + i]], 1);
}

__global__ void scan_block_kernel(const int* __restrict__ deg, int* __restrict__ offs,
                                  int* __restrict__ bsum, int n) {
    __shared__ int ws[8];
    int t = threadIdx.x, lane = t & 31, w = t >> 5;
    int i = blockIdx.x * 256 + t;
    int v = (i < n) ? deg[i] : 0;
    int x = v;
#pragma unroll
    for (int o = 1; o < 32; o <<= 1) {
        int tv = __shfl_up_sync(0xffffffffu, x, o);
        if (lane >= o) x += tv;
    }
    if (lane == 31) ws[w] = x;
    __syncthreads();
    if (w == 0) {
        int y = (lane < 8) ? ws[lane] : 0;
#pragma unroll
        for (int o = 1; o < 8; o <<= 1) {
            int tv = __shfl_up_sync(0xffffffffu, y, o);
            if (lane >= o) y += tv;
        }
        if (lane < 8) ws[lane] = y;
    }
    __syncthreads();
    int woff = w ? ws[w - 1] : 0;
    if (i < n) offs[i] = woff + x - v;
    if (t == 255) bsum[blockIdx.x] = ws[7];
}

__global__ void scan_add_kernel(int* __restrict__ offs, int* __restrict__ cursor,
                                const int* __restrict__ bsum, int n, int nb) {
    __shared__ int ws[8];
    __shared__ int s_total;
    int t = threadIdx.x, lane = t & 31, w = t >> 5;
    int bid = blockIdx.x;
    int v = (t < nb && t < bid) ? bsum[t] : 0;
#pragma unroll
    for (int o = 16; o; o >>= 1) v += __shfl_xor_sync(0xffffffffu, v, o);
    if (lane == 0) ws[w] = v;
    __syncthreads();
    if (t == 0) {
        int s = 0;
#pragma unroll
        for (int k = 0; k < 8; k++) s += ws[k];
        s_total = s;
    }
    __syncthreads();
    int i = bid * 256 + t;
    if (i < n) {
        int o = offs[i] + s_total;
        offs[i] = o;
        cursor[i] = o;
    }
}

__global__ void scatter_kernel(const int* __restrict__ ei, int* __restrict__ cursor,
                               int* __restrict__ csr_src, int E) {
    int i = blockIdx.x * blockDim.x + threadIdx.x;
    if (i >= E) return;
    int s = ei[i];
    int d = ei[E + i];
    int p = atomicAdd(&cursor[d], 1);
    csr_src[p] = s;
}

// ---------------- fp16 MMA GEMM: CTA 128x64, warp 16x64, 3-stage cp.async ----------------
__device__ __forceinline__ void mma_f16(float* c, const unsigned* a, unsigned b0, unsigned b1) {
    asm volatile(
        "mma.sync.aligned.m16n8k16.row.col.f32.f16.f16.f32 "
        "{%0,%1,%2,%3},{%4,%5,%6,%7},{%8,%9},{%0,%1,%2,%3};"
        : "+f"(c[0]), "+f"(c[1]), "+f"(c[2]), "+f"(c[3])
        : "r"(a[0]), "r"(a[1]), "r"(a[2]), "r"(a[3]), "r"(b0), "r"(b1));
}

__device__ __forceinline__ void ldsm_x4(unsigned& r0, unsigned& r1, unsigned& r2, unsigned& r3,
                                        unsigned addr) {
    asm volatile("ldmatrix.sync.aligned.m8n8.x4.shared.b16 {%0,%1,%2,%3}, [%4];"
                 : "=r"(r0), "=r"(r1), "=r"(r2), "=r"(r3) : "r"(addr));
}

__device__ __forceinline__ void ldsm_x4t(unsigned& r0, unsigned& r1, unsigned& r2, unsigned& r3,
                                         unsigned addr) {
    asm volatile("ldmatrix.sync.aligned.m8n8.x4.trans.shared.b16 {%0,%1,%2,%3}, [%4];"
                 : "=r"(r0), "=r"(r1), "=r"(r2), "=r"(r3) : "r"(addr));
}

__device__ __forceinline__ void cpasync16(void* dst_smem, const void* src, bool pred) {
    unsigned d = (unsigned)__cvta_generic_to_shared(dst_smem);
    int sz = pred ? 16 : 0;
    asm volatile("cp.async.cg.shared.global [%0], [%1], 16, %2;\n" :: "r"(d), "l"(src), "r"(sz));
}

#define GBM 128
#define GBN 64
#define GBK 32
#define STAGES 3
#define APITCH 40
#define BPITCH 72
#define ABUF (GBM * APITCH)
#define BBUF (GBK * BPITCH)
#define GEMM_SMEM ((STAGES * (ABUF + BBUF)) * 2)

__global__ __launch_bounds__(256, 3) void mma_gemm_kernel(const __half* __restrict__ A,
                                                          const __half* __restrict__ B,
                                                          __half* __restrict__ C,
                                                          const float* __restrict__ a_src,
                                                          const float* __restrict__ a_dst,
                                                          float* __restrict__ as_out,
                                                          float* __restrict__ ad_out,
                                                          int M, int K) {
    extern __shared__ __half smem[];
    __half* sA = smem;
    __half* sB = smem + STAGES * ABUF;
    int tid = threadIdx.x;
    int bm = blockIdx.x * GBM, bn = blockIdx.y * GBN;
    int lane = tid & 31, wid = tid >> 5;
    int g = lane >> 2, l4 = lane & 3;

    float acc[8][4];
#pragma unroll
    for (int nt = 0; nt < 8; nt++)
#pragma unroll
        for (int c = 0; c < 4; c++) acc[nt][c] = 0.f;

    int T = K / GBK;
    unsigned sAu = (unsigned)__cvta_generic_to_shared(sA);
    unsigned sBu = (unsigned)__cvta_generic_to_shared(sB);
    int lrow = (lane & 7) + ((lane >> 3) & 1) * 8;
    int lcol8 = (lane >> 4) * 8;

#define LOAD_TILE(buf, k0)                                                              \
    {                                                                                   \
        __half* a_ = sA + (buf) * ABUF;                                                 \
        __half* b_ = sB + (buf) * BBUF;                                                 \
        _Pragma("unroll")                                                               \
        for (int i = 0; i < 2; i++) {                                                   \
            int idx = tid + i * 256;                                                    \
            int row = idx >> 2, kc = idx & 3;                                           \
            int gr = bm + row;                                                          \
            bool p = gr < M;                                                            \
            int grc = p ? gr : 0;                                                       \
            cpasync16(&a_[row * APITCH + kc * 8], &A[(size_t)grc * K + (k0) + kc * 8], p); \
        }                                                                               \
        {                                                                               \
            int r = tid >> 3, c = tid & 7;                                              \
            cpasync16(&b_[r * BPITCH + c * 8], &B[(size_t)((k0) + r) * 256 + bn + c * 8], true); \
        }                                                                               \
        asm volatile("cp.async.commit_group;\n");                                       \
    }

    LOAD_TILE(0, 0)
    if (T > 1) LOAD_TILE(1, GBK)

    for (int t = 0; t < T; t++) {
        if (t + 1 < T) {
            asm volatile("cp.async.wait_group 1;\n");
        } else {
            asm volatile("cp.async.wait_group 0;\n");
        }
        __syncthreads();

        if (t + 2 < T) LOAD_TILE((t + 2) % STAGES, (t + 2) * GBK)

        int cb = t % STAGES;
        unsigned aBase = sAu + cb * ABUF * 2;
        unsigned bBase = sBu + cb * BBUF * 2;
#pragma unroll
        for (int ks = 0; ks < 2; ks++) {
            int kb = ks * 16;
            unsigned a[4];
            {
                int row = wid * 16 + lrow;
                ldsm_x4(a[0], a[1], a[2], a[3], aBase + (row * APITCH + kb + lcol8) * 2);
            }
#pragma unroll
            for (int nt2 = 0; nt2 < 4; nt2++) {
                int n0 = nt2 * 16;
                unsigned b0, b1, b2, b3;
                ldsm_x4t(b0, b1, b2, b3, bBase + ((kb + lrow) * BPITCH + n0 + lcol8) * 2);
                mma_f16(acc[nt2 * 2], a, b0, b1);
                mma_f16(acc[nt2 * 2 + 1], a, b2, b3);
            }
        }
    }

#pragma unroll
    for (int nt = 0; nt < 8; nt++) {
        int row0 = bm + wid * 16 + g;
        int col = bn + nt * 8 + l4 * 2;
        if (row0 < M)
            *(__half2*)&C[(size_t)row0 * 256 + col] = __floats2half2_rn(acc[nt][0], acc[nt][1]);
        if (row0 + 8 < M)
            *(__half2*)&C[(size_t)(row0 + 8) * 256 + col] = __floats2half2_rn(acc[nt][2], acc[nt][3]);
    }

    int head = bn >> 6;
    const float* asv = a_src + head * 64;
    const float* adv = a_dst + head * 64;
    {
        float sA_ = 0.f, dA_ = 0.f, sB_ = 0.f, dB_ = 0.f;
#pragma unroll
        for (int nt = 0; nt < 8; nt++) {
            int lc = nt * 8 + l4 * 2;
            float w0 = __ldg(&asv[lc]), w1 = __ldg(&asv[lc + 1]);
            float u0 = __ldg(&adv[lc]), u1 = __ldg(&adv[lc + 1]);
            sA_ += acc[nt][0] * w0 + acc[nt][1] * w1;
            dA_ += acc[nt][0] * u0 + acc[nt][1] * u1;
            sB_ += acc[nt][2] * w0 + acc[nt][3] * w1;
            dB_ += acc[nt][2] * u0 + acc[nt][3] * u1;
        }
#pragma unroll
        for (int o = 1; o < 4; o <<= 1) {
            sA_ += __shfl_xor_sync(0xffffffffu, sA_, o);
            dA_ += __shfl_xor_sync(0xffffffffu, dA_, o);
            sB_ += __shfl_xor_sync(0xffffffffu, sB_, o);
            dB_ += __shfl_xor_sync(0xffffffffu, dB_, o);
        }
        if (l4 == 0) {
            int row0 = bm + wid * 16 + g;
            if (row0 < M) {
                as_out[row0 * 4 + head] = sA_;
                ad_out[row0 * 4 + head] = dA_;
            }
            if (row0 + 8 < M) {
                as_out[(row0 + 8) * 4 + head] = sB_;
                ad_out[(row0 + 8) * 4 + head] = dB_;
            }
        }
    }
}

__device__ __forceinline__ float lrelu(float v) { return v > 0.f ? v : 0.2f * v; }

// ---------------- warp-per-node aggregation, no-max softmax ----------------
// final==0: write fp16 out (relu'd).
// final==1: skip out store; compute h3 = relu(out)@W3 [256x2] in-warp, writing
//           h3 / as3 / ad3 into DEDICATED buffers (no aliasing with as/ad read here).
__global__ __launch_bounds__(256) void agg_warp_kernel(const __half* __restrict__ h,
                                                       const int* __restrict__ csr_src,
                                                       const int* __restrict__ offs,
                                                       const int* __restrict__ deg,
                                                       const float* __restrict__ as,
                                                       const float* __restrict__ ad,
                                                       const float* __restrict__ bias,
                                                       __half* __restrict__ out,
                                                       const float* __restrict__ W3,
                                                       const float* __restrict__ a_s3,
                                                       const float* __restrict__ a_d3,
                                                       float* __restrict__ h3_out,
                                                       float* __restrict__ as3_out,
                                                       float* __restrict__ ad3_out,
                                                       int n, int final_layer) {
    int node = (blockIdx.x * blockDim.x + threadIdx.x) >> 5;
    int lane = threadIdx.x & 31;
    if (node >= n) return;
    int myhead = lane >> 3;
    int j = lane & 3;
    int i = lane >> 2;
    int st = offs[node], d = deg[node];
    float adn = ad[node * 4 + j];

    float z = 0.f;
    float4 acc0 = make_float4(0.f, 0.f, 0.f, 0.f);
    float4 acc1 = make_float4(0.f, 0.f, 0.f, 0.f);

    for (int base = 0; base < d; base += 8) {
        int cnt = min(8, d - base);
        int src = (lane < cnt) ? csr_src[st + base + lane] : 0;
        int s_i = __shfl_sync(0xffffffffu, src, i);
        float p = (i < cnt) ? __expf(lrelu(as[s_i * 4 + j] + adn)) : 0.f;
        z += p;
#pragma unroll 8
        for (int q = 0; q < cnt; q++) {
            int s = __shfl_sync(0xffffffffu, src, q);
            float pq = __shfl_sync(0xffffffffu, p, q * 4 + myhead);
            uint4 hv = *(const uint4*)(h + (size_t)s * 256 + lane * 8);
            float2 f0 = __half22float2(*(__half2*)&hv.x);
            float2 f1 = __half22float2(*(__half2*)&hv.y);
            float2 f2 = __half22float2(*(__half2*)&hv.z);
            float2 f3 = __half22float2(*(__half2*)&hv.w);
            acc0.x += pq * f0.x; acc0.y += pq * f0.y;
            acc0.z += pq * f1.x; acc0.w += pq * f1.y;
            acc1.x += pq * f2.x; acc1.y += pq * f2.y;
            acc1.z += pq * f3.x; acc1.w += pq * f3.y;
        }
    }
#pragma unroll
    for (int o = 4; o < 32; o <<= 1) z += __shfl_xor_sync(0xffffffffu, z, o);
    float z_my = __shfl_sync(0xffffffffu, z, myhead * 5);
    float rz = 1.f / (z_my + 1e-16f);
    const float4* bp = (const float4*)(bias + lane * 8);
    float4 b0 = bp[0], b1 = bp[1];
    float4 o0, o1;
    o0.x = fmaxf(acc0.x * rz + b0.x, 0.f); o0.y = fmaxf(acc0.y * rz + b0.y, 0.f);
    o0.z = fmaxf(acc0.z * rz + b0.z, 0.f); o0.w = fmaxf(acc0.w * rz + b0.w, 0.f);
    o1.x = fmaxf(acc1.x * rz + b1.x, 0.f); o1.y = fmaxf(acc1.y * rz + b1.y, 0.f);
    o1.z = fmaxf(acc1.z * rz + b1.z, 0.f); o1.w = fmaxf(acc1.w * rz + b1.w, 0.f);

    if (!final_layer) {
        uint4 pk;
        *(__half2*)&pk.x = __floats2half2_rn(o0.x, o0.y);
        *(__half2*)&pk.y = __floats2half2_rn(o0.z, o0.w);
        *(__half2*)&pk.z = __floats2half2_rn(o1.x, o1.y);
        *(__half2*)&pk.w = __floats2half2_rn(o1.z, o1.w);
        *(uint4*)(out + (size_t)node * 256 + lane * 8) = pk;
    } else {
        // fused layer-3 GEMM: h3 = relu(out) @ W3 [256,2]
        int cb = lane * 8;
        float a0 = 0.f, a1 = 0.f;
        float vv[8] = {o0.x, o0.y, o0.z, o0.w, o1.x, o1.y, o1.z, o1.w};
#pragma unroll
        for (int c = 0; c < 8; c++) {
            float w0 = __ldg(&W3[(cb + c) * 2]);
            float w1 = __ldg(&W3[(cb + c) * 2 + 1]);
            a0 += vv[c] * w0;
            a1 += vv[c] * w1;
        }
#pragma unroll
        for (int o = 16; o; o >>= 1) {
            a0 += __shfl_xor_sync(0xffffffffu, a0, o);
            a1 += __shfl_xor_sync(0xffffffffu, a1, o);
        }
        if (lane == 0) {
            h3_out[2 * node] = a0;
            h3_out[2 * node + 1] = a1;
            as3_out[node] = a0 * __ldg(&a_s3[0]) + a1 * __ldg(&a_s3[1]);
            ad3_out[node] = a0 * __ldg(&a_d3[0]) + a1 * __ldg(&a_d3[1]);
        }
    }
}

// ---------------- layer3 aggregation, no-max softmax (H=1, C=2) ----------------
__global__ void agg3_fused_kernel(const float* __restrict__ h3, const int* __restrict__ csr_src,
                                  const int* __restrict__ offs, const int* __restrict__ deg,
                                  const float* __restrict__ as, const float* __restrict__ ad,
                                  const float* __restrict__ bias, float* __restrict__ out, int n) {
    int i = blockIdx.x * blockDim.x + threadIdx.x;
    if (i >= n) return;
    int st = offs[i], d = deg[i];
    float adn = ad[i];
    float zt = 0.f;
    float a0 = 0.f, a1 = 0.f;
    for (int k = 0; k < d; k++) {
        int s = csr_src[st + k];
        float p = __expf(lrelu(as[s] + adn));
        zt += p;
        a0 += p * h3[2 * s];
        a1 += p * h3[2 * s + 1];
    }
    float rz = 1.f / (zt + 1e-16f);
    out[2 * i] = a0 * rz + bias[0];
    out[2 * i + 1] = a1 * rz + bias[1];
}

// ---------------- launcher ----------------
extern "C" void kernel_launch(void* const* d_in, const int* in_sizes, int n_in,
                              void* d_out, int out_size) {
    const float* x   = (const float*)d_in[0];
    const int*   ei  = (const int*)d_in[1];
    const float* W1  = (const float*)d_in[2];
    const float* as1 = (const float*)d_in[3];
    const float* ad1 = (const float*)d_in[4];
    const float* b1  = (const float*)d_in[5];
    const float* W2  = (const float*)d_in[6];
    const float* as2 = (const float*)d_in[7];
    const float* ad2 = (const float*)d_in[8];
    const float* b2  = (const float*)d_in[9];
    const float* W3  = (const float*)d_in[10];
    const float* as3 = (const float*)d_in[11];
    const float* ad3 = (const float*)d_in[12];
    const float* b3  = (const float*)d_in[13];
    float* outp = (float*)d_out;

    int n = in_sizes[0] / 128;
    int E = in_sizes[1] / 2;

    __half *hbuf, *aggbuf, *xh, *w1h, *w2h;
    float *h3, *as, *ad, *as3b, *ad3b;
    int *deg, *offs, *cursor, *bsum, *csr_src;
    cudaGetSymbolAddress((void**)&hbuf, g_hbuf);
    cudaGetSymbolAddress((void**)&aggbuf, g_aggbuf);
    cudaGetSymbolAddress((void**)&xh, g_xh);
    cudaGetSymbolAddress((void**)&w1h, g_w1h);
    cudaGetSymbolAddress((void**)&w2h, g_w2h);
    cudaGetSymbolAddress((void**)&h3, g_h3);
    cudaGetSymbolAddress((void**)&as, g_as);
    cudaGetSymbolAddress((void**)&ad, g_ad);
    cudaGetSymbolAddress((void**)&as3b, g_as3);
    cudaGetSymbolAddress((void**)&ad3b, g_ad3);
    cudaGetSymbolAddress((void**)&deg, g_deg);
    cudaGetSymbolAddress((void**)&offs, g_offs);
    cudaGetSymbolAddress((void**)&cursor, g_cursor);
    cudaGetSymbolAddress((void**)&bsum, g_bsum);
    cudaGetSymbolAddress((void**)&csr_src, g_csr_src);

    cudaFuncSetAttribute(mma_gemm_kernel, cudaFuncAttributeMaxDynamicSharedMemorySize, GEMM_SMEM);

    int nb = cdiv(n, 256);
    dim3 gemm_grid(cdiv(n, 128), 4);
    int agg_blocks = cdiv(n * 32, 256);

    // fork side stream for CSR build (overlap with converts + GEMM1)
    cudaStream_t sB;
    cudaStreamCreateWithFlags(&sB, cudaStreamNonBlocking);
    cudaEvent_t eFork, eJoin;
    cudaEventCreateWithFlags(&eFork, cudaEventDisableTiming);
    cudaEventCreateWithFlags(&eJoin, cudaEventDisableTiming);
    cudaEventRecord(eFork, 0);
    cudaStreamWaitEvent(sB, eFork, 0);

    // main stream: converts + GEMM1
    f32_to_f16_kernel<<<cdiv(n * 128 / 4, 256), 256>>>(x, xh, n * 128 / 4);
    f32_to_f16_kernel<<<cdiv(128 * 256 / 4, 256), 256>>>(W1, w1h, 128 * 256 / 4);
    f32_to_f16_kernel<<<cdiv(256 * 256 / 4, 256), 256>>>(W2, w2h, 256 * 256 / 4);
    mma_gemm_kernel<<<gemm_grid, 256, GEMM_SMEM>>>(xh, w1h, hbuf, as1, ad1, as, ad, n, 128);

    // side stream: CSR build
    fill_i32<<<cdiv(n, 256), 256, 0, sB>>>(deg, 0, n);
    hist_kernel<<<cdiv(E, 256), 256, 0, sB>>>(ei, deg, E);
    scan_block_kernel<<<nb, 256, 0, sB>>>(deg, offs, bsum, n);
    scan_add_kernel<<<nb, 256, 0, sB>>>(offs, cursor, bsum, n, nb);
    scatter_kernel<<<cdiv(E, 256), 256, 0, sB>>>(ei, cursor, csr_src, E);
    cudaEventRecord(eJoin, sB);
    cudaStreamWaitEvent(0, eJoin, 0);

    // Layer 1 aggregation (writes fp16 aggbuf)
    agg_warp_kernel<<<agg_blocks, 256>>>(hbuf, csr_src, offs, deg, as, ad, b1, aggbuf,
                                         nullptr, nullptr, nullptr, nullptr, nullptr, nullptr,
                                         n, 0);

    // Layer 2 GEMM
    mma_gemm_kernel<<<gemm_grid, 256, GEMM_SMEM>>>(aggbuf, w2h, hbuf, as2, ad2, as, ad, n, 256);

    // Layer 2 aggregation fused with layer-3 GEMM + alpha (separate as3/ad3 buffers)
    agg_warp_kernel<<<agg_blocks, 256>>>(hbuf, csr_src, offs, deg, as, ad, b2, nullptr,
                                         W3, as3, ad3, h3, as3b, ad3b,
                                         n, 1);

    // Layer 3 edge phase
    agg3_fused_kernel<<<cdiv(n, 256), 256>>>(h3, csr_src, offs, deg, as3b, ad3b, b3, outp, n);
}

// round 17
// speedup vs baseline: 1.1688x; 1.1688x over previous
#include <cuda_runtime.h>
#include <cuda_fp16.h>
#include <math.h>
#include <limits.h>

#define NMAX 50000
#define EMAX 800000
#define HCMAX 256

// ---------------- scratch ----------------
__device__ __half g_hbuf[NMAX * HCMAX];
__device__ __half g_aggbuf[NMAX * HCMAX];
__device__ __half g_xh[NMAX * 128];
__device__ __half g_w1h[128 * 256];
__device__ __half g_w2h[256 * 256];
__device__ float g_h3[NMAX * 2];
__device__ float g_as[NMAX * 4];
__device__ float g_ad[NMAX * 4];
__device__ float g_as3[NMAX];
__device__ float g_ad3[NMAX];
__device__ int   g_deg[NMAX];
__device__ int   g_offs[NMAX];
__device__ int   g_cursor[NMAX];
__device__ int   g_bsum[256];
__device__ int   g_csr_src[EMAX];

static inline int cdiv(int a, int b) { return (a + b - 1) / b; }

// ---------------- fp32 -> fp16 convert ----------------
__global__ void f32_to_f16_kernel(const float* __restrict__ in, __half* __restrict__ out, int n4) {
    int i = blockIdx.x * blockDim.x + threadIdx.x;
    if (i >= n4) return;
    float4 v = ((const float4*)in)[i];
    ((__half2*)out)[i * 2] = __floats2half2_rn(v.x, v.y);
    ((__half2*)out)[i * 2 + 1] = __floats2half2_rn(v.z, v.w);
}

// ---------------- utility ----------------
__global__ void fill_i32(int* p, int v, int n) {
    int i = blockIdx.x * blockDim.x + threadIdx.x;
    if (i < n) p[i] = v;
}

// ---------------- CSR build ----------------
__global__ void hist_kernel(const int* __restrict__ ei, int* __restrict__ deg, int E) {
    int i = blockIdx.x * blockDim.x + threadIdx.x;
    if (i < E) atomicAdd(&deg[ei[E + i]], 1);
}

__global__ void scan_block_kernel(const int* __restrict__ deg, int* __restrict__ offs,
                                  int* __restrict__ bsum, int n) {
    __shared__ int ws[8];
    int t = threadIdx.x, lane = t & 31, w = t >> 5;
    int i = blockIdx.x * 256 + t;
    int v = (i < n) ? deg[i] : 0;
    int x = v;
#pragma unroll
    for (int o = 1; o < 32; o <<= 1) {
        int tv = __shfl_up_sync(0xffffffffu, x, o);
        if (lane >= o) x += tv;
    }
    if (lane == 31) ws[w] = x;
    __syncthreads();
    if (w == 0) {
        int y = (lane < 8) ? ws[lane] : 0;
#pragma unroll
        for (int o = 1; o < 8; o <<= 1) {
            int tv = __shfl_up_sync(0xffffffffu, y, o);
            if (lane >= o) y += tv;
        }
        if (lane < 8) ws[lane] = y;
    }
    __syncthreads();
    int woff = w ? ws[w - 1] : 0;
    if (i < n) offs[i] = woff + x - v;
    if (t == 255) bsum[blockIdx.x] = ws[7];
}

__global__ void scan_add_kernel(int* __restrict__ offs, int* __restrict__ cursor,
                                const int* __restrict__ bsum, int n, int nb) {
    __shared__ int ws[8];
    __shared__ int s_total;
    int t = threadIdx.x, lane = t & 31, w = t >> 5;
    int bid = blockIdx.x;
    int v = (t < nb && t < bid) ? bsum[t] : 0;
#pragma unroll
    for (int o = 16; o; o >>= 1) v += __shfl_xor_sync(0xffffffffu, v, o);
    if (lane == 0) ws[w] = v;
    __syncthreads();
    if (t == 0) {
        int s = 0;
#pragma unroll
        for (int k = 0; k < 8; k++) s += ws[k];
        s_total = s;
    }
    __syncthreads();
    int i = bid * 256 + t;
    if (i < n) {
        int o = offs[i] + s_total;
        offs[i] = o;
        cursor[i] = o;
    }
}

__global__ void scatter_kernel(const int* __restrict__ ei, int* __restrict__ cursor,
                               int* __restrict__ csr_src, int E) {
    int i = blockIdx.x * blockDim.x + threadIdx.x;
    if (i >= E) return;
    int s = ei[i];
    int d = ei[E + i];
    int p = atomicAdd(&cursor[d], 1);
    csr_src[p] = s;
}

// ---------------- fp16 MMA GEMM: CTA 128x64, warp 16x64, 3-stage cp.async ----------------
__device__ __forceinline__ void mma_f16(float* c, const unsigned* a, unsigned b0, unsigned b1) {
    asm volatile(
        "mma.sync.aligned.m16n8k16.row.col.f32.f16.f16.f32 "
        "{%0,%1,%2,%3},{%4,%5,%6,%7},{%8,%9},{%0,%1,%2,%3};"
        : "+f"(c[0]), "+f"(c[1]), "+f"(c[2]), "+f"(c[3])
        : "r"(a[0]), "r"(a[1]), "r"(a[2]), "r"(a[3]), "r"(b0), "r"(b1));
}

__device__ __forceinline__ void ldsm_x4(unsigned& r0, unsigned& r1, unsigned& r2, unsigned& r3,
                                        unsigned addr) {
    asm volatile("ldmatrix.sync.aligned.m8n8.x4.shared.b16 {%0,%1,%2,%3}, [%4];"
                 : "=r"(r0), "=r"(r1), "=r"(r2), "=r"(r3) : "r"(addr));
}

__device__ __forceinline__ void ldsm_x4t(unsigned& r0, unsigned& r1, unsigned& r2, unsigned& r3,
                                         unsigned addr) {
    asm volatile("ldmatrix.sync.aligned.m8n8.x4.trans.shared.b16 {%0,%1,%2,%3}, [%4];"
                 : "=r"(r0), "=r"(r1), "=r"(r2), "=r"(r3) : "r"(addr));
}

__device__ __forceinline__ void cpasync16(void* dst_smem, const void* src, bool pred) {
    unsigned d = (unsigned)__cvta_generic_to_shared(dst_smem);
    int sz = pred ? 16 : 0;
    asm volatile("cp.async.cg.shared.global [%0], [%1], 16, %2;\n" :: "r"(d), "l"(src), "r"(sz));
}

#define GBM 128
#define GBN 64
#define GBK 32
#define STAGES 3
#define APITCH 40
#define BPITCH 72
#define ABUF (GBM * APITCH)
#define BBUF (GBK * BPITCH)
#define GEMM_SMEM ((STAGES * (ABUF + BBUF)) * 2)

__global__ __launch_bounds__(256, 3) void mma_gemm_kernel(const __half* __restrict__ A,
                                                          const __half* __restrict__ B,
                                                          __half* __restrict__ C,
                                                          const float* __restrict__ a_src,
                                                          const float* __restrict__ a_dst,
                                                          float* __restrict__ as_out,
                                                          float* __restrict__ ad_out,
                                                          int M, int K) {
    extern __shared__ __half smem[];
    __half* sA = smem;
    __half* sB = smem + STAGES * ABUF;
    int tid = threadIdx.x;
    int bm = blockIdx.x * GBM, bn = blockIdx.y * GBN;
    int lane = tid & 31, wid = tid >> 5;
    int g = lane >> 2, l4 = lane & 3;

    float acc[8][4];
#pragma unroll
    for (int nt = 0; nt < 8; nt++)
#pragma unroll
        for (int c = 0; c < 4; c++) acc[nt][c] = 0.f;

    int T = K / GBK;
    unsigned sAu = (unsigned)__cvta_generic_to_shared(sA);
    unsigned sBu = (unsigned)__cvta_generic_to_shared(sB);
    int lrow = (lane & 7) + ((lane >> 3) & 1) * 8;
    int lcol8 = (lane >> 4) * 8;

#define LOAD_TILE(buf, k0)                                                              \
    {                                                                                   \
        __half* a_ = sA + (buf) * ABUF;                                                 \
        __half* b_ = sB + (buf) * BBUF;                                                 \
        _Pragma("unroll")                                                               \
        for (int i = 0; i < 2; i++) {                                                   \
            int idx = tid + i * 256;                                                    \
            int row = idx >> 2, kc = idx & 3;                                           \
            int gr = bm + row;                                                          \
            bool p = gr < M;                                                            \
            int grc = p ? gr : 0;                                                       \
            cpasync16(&a_[row * APITCH + kc * 8], &A[(size_t)grc * K + (k0) + kc * 8], p); \
        }                                                                               \
        {                                                                               \
            int r = tid >> 3, c = tid & 7;                                              \
            cpasync16(&b_[r * BPITCH + c * 8], &B[(size_t)((k0) + r) * 256 + bn + c * 8], true); \
        }                                                                               \
        asm volatile("cp.async.commit_group;\n");                                       \
    }

    LOAD_TILE(0, 0)
    if (T > 1) LOAD_TILE(1, GBK)

    for (int t = 0; t < T; t++) {
        if (t + 1 < T) {
            asm volatile("cp.async.wait_group 1;\n");
        } else {
            asm volatile("cp.async.wait_group 0;\n");
        }
        __syncthreads();

        if (t + 2 < T) LOAD_TILE((t + 2) % STAGES, (t + 2) * GBK)

        int cb = t % STAGES;
        unsigned aBase = sAu + cb * ABUF * 2;
        unsigned bBase = sBu + cb * BBUF * 2;
#pragma unroll
        for (int ks = 0; ks < 2; ks++) {
            int kb = ks * 16;
            unsigned a[4];
            {
                int row = wid * 16 + lrow;
                ldsm_x4(a[0], a[1], a[2], a[3], aBase + (row * APITCH + kb + lcol8) * 2);
            }
#pragma unroll
            for (int nt2 = 0; nt2 < 4; nt2++) {
                int n0 = nt2 * 16;
                unsigned b0, b1, b2, b3;
                ldsm_x4t(b0, b1, b2, b3, bBase + ((kb + lrow) * BPITCH + n0 + lcol8) * 2);
                mma_f16(acc[nt2 * 2], a, b0, b1);
                mma_f16(acc[nt2 * 2 + 1], a, b2, b3);
            }
        }
    }

#pragma unroll
    for (int nt = 0; nt < 8; nt++) {
        int row0 = bm + wid * 16 + g;
        int col = bn + nt * 8 + l4 * 2;
        if (row0 < M)
            *(__half2*)&C[(size_t)row0 * 256 + col] = __floats2half2_rn(acc[nt][0], acc[nt][1]);
        if (row0 + 8 < M)
            *(__half2*)&C[(size_t)(row0 + 8) * 256 + col] = __floats2half2_rn(acc[nt][2], acc[nt][3]);
    }

    int head = bn >> 6;
    const float* asv = a_src + head * 64;
    const float* adv = a_dst + head * 64;
    {
        float sA_ = 0.f, dA_ = 0.f, sB_ = 0.f, dB_ = 0.f;
#pragma unroll
        for (int nt = 0; nt < 8; nt++) {
            int lc = nt * 8 + l4 * 2;
            float w0 = __ldg(&asv[lc]), w1 = __ldg(&asv[lc + 1]);
            float u0 = __ldg(&adv[lc]), u1 = __ldg(&adv[lc + 1]);
            sA_ += acc[nt][0] * w0 + acc[nt][1] * w1;
            dA_ += acc[nt][0] * u0 + acc[nt][1] * u1;
            sB_ += acc[nt][2] * w0 + acc[nt][3] * w1;
            dB_ += acc[nt][2] * u0 + acc[nt][3] * u1;
        }
#pragma unroll
        for (int o = 1; o < 4; o <<= 1) {
            sA_ += __shfl_xor_sync(0xffffffffu, sA_, o);
            dA_ += __shfl_xor_sync(0xffffffffu, dA_, o);
            sB_ += __shfl_xor_sync(0xffffffffu, sB_, o);
            dB_ += __shfl_xor_sync(0xffffffffu, dB_, o);
        }
        if (l4 == 0) {
            int row0 = bm + wid * 16 + g;
            if (row0 < M) {
                as_out[row0 * 4 + head] = sA_;
                ad_out[row0 * 4 + head] = dA_;
            }
            if (row0 + 8 < M) {
                as_out[(row0 + 8) * 4 + head] = sB_;
                ad_out[(row0 + 8) * 4 + head] = dB_;
            }
        }
    }
}

__device__ __forceinline__ float lrelu(float v) { return v > 0.f ? v : 0.2f * v; }

// ---------------- warp-per-node aggregation, no-max softmax (R12 winner, unchanged) ----------------
__global__ __launch_bounds__(256) void agg_warp_kernel(const __half* __restrict__ h,
                                                       const int* __restrict__ csr_src,
                                                       const int* __restrict__ offs,
                                                       const int* __restrict__ deg,
                                                       const float* __restrict__ as,
                                                       const float* __restrict__ ad,
                                                       const float* __restrict__ bias,
                                                       __half* __restrict__ out,
                                                       int n, int do_relu) {
    int node = (blockIdx.x * blockDim.x + threadIdx.x) >> 5;
    int lane = threadIdx.x & 31;
    if (node >= n) return;
    int myhead = lane >> 3;
    int j = lane & 3;
    int i = lane >> 2;
    int st = offs[node], d = deg[node];
    float adn = ad[node * 4 + j];

    float z = 0.f;
    float4 acc0 = make_float4(0.f, 0.f, 0.f, 0.f);
    float4 acc1 = make_float4(0.f, 0.f, 0.f, 0.f);

    for (int base = 0; base < d; base += 8) {
        int cnt = min(8, d - base);
        int src = (lane < cnt) ? csr_src[st + base + lane] : 0;
        int s_i = __shfl_sync(0xffffffffu, src, i);
        float p = (i < cnt) ? __expf(lrelu(as[s_i * 4 + j] + adn)) : 0.f;
        z += p;
#pragma unroll 8
        for (int q = 0; q < cnt; q++) {
            int s = __shfl_sync(0xffffffffu, src, q);
            float pq = __shfl_sync(0xffffffffu, p, q * 4 + myhead);
            uint4 hv = *(const uint4*)(h + (size_t)s * 256 + lane * 8);
            float2 f0 = __half22float2(*(__half2*)&hv.x);
            float2 f1 = __half22float2(*(__half2*)&hv.y);
            float2 f2 = __half22float2(*(__half2*)&hv.z);
            float2 f3 = __half22float2(*(__half2*)&hv.w);
            acc0.x += pq * f0.x; acc0.y += pq * f0.y;
            acc0.z += pq * f1.x; acc0.w += pq * f1.y;
            acc1.x += pq * f2.x; acc1.y += pq * f2.y;
            acc1.z += pq * f3.x; acc1.w += pq * f3.y;
        }
    }
#pragma unroll
    for (int o = 4; o < 32; o <<= 1) z += __shfl_xor_sync(0xffffffffu, z, o);
    float z_my = __shfl_sync(0xffffffffu, z, myhead * 5);
    float rz = 1.f / (z_my + 1e-16f);
    const float4* bp = (const float4*)(bias + lane * 8);
    float4 b0 = bp[0], b1 = bp[1];
    float4 o0, o1;
    o0.x = acc0.x * rz + b0.x; o0.y = acc0.y * rz + b0.y;
    o0.z = acc0.z * rz + b0.z; o0.w = acc0.w * rz + b0.w;
    o1.x = acc1.x * rz + b1.x; o1.y = acc1.y * rz + b1.y;
    o1.z = acc1.z * rz + b1.z; o1.w = acc1.w * rz + b1.w;
    if (do_relu) {
        o0.x = fmaxf(o0.x, 0.f); o0.y = fmaxf(o0.y, 0.f);
        o0.z = fmaxf(o0.z, 0.f); o0.w = fmaxf(o0.w, 0.f);
        o1.x = fmaxf(o1.x, 0.f); o1.y = fmaxf(o1.y, 0.f);
        o1.z = fmaxf(o1.z, 0.f); o1.w = fmaxf(o1.w, 0.f);
    }
    uint4 pk;
    *(__half2*)&pk.x = __floats2half2_rn(o0.x, o0.y);
    *(__half2*)&pk.y = __floats2half2_rn(o0.z, o0.w);
    *(__half2*)&pk.z = __floats2half2_rn(o1.x, o1.y);
    *(__half2*)&pk.w = __floats2half2_rn(o1.z, o1.w);
    *(uint4*)(out + (size_t)node * 256 + lane * 8) = pk;
}

// ---------------- layer-2 aggregation with fused layer-3 GEMM (separate kernel) ----------------
__global__ __launch_bounds__(256) void agg_warp_final_kernel(const __half* __restrict__ h,
                                                             const int* __restrict__ csr_src,
                                                             const int* __restrict__ offs,
                                                             const int* __restrict__ deg,
                                                             const float* __restrict__ as,
                                                             const float* __restrict__ ad,
                                                             const float* __restrict__ bias,
                                                             const float* __restrict__ W3,
                                                             const float* __restrict__ a_s3,
                                                             const float* __restrict__ a_d3,
                                                             float* __restrict__ h3_out,
                                                             float* __restrict__ as3_out,
                                                             float* __restrict__ ad3_out,
                                                             int n) {
    int node = (blockIdx.x * blockDim.x + threadIdx.x) >> 5;
    int lane = threadIdx.x & 31;
    if (node >= n) return;
    int myhead = lane >> 3;
    int j = lane & 3;
    int i = lane >> 2;
    int st = offs[node], d = deg[node];
    float adn = ad[node * 4 + j];

    float z = 0.f;
    float4 acc0 = make_float4(0.f, 0.f, 0.f, 0.f);
    float4 acc1 = make_float4(0.f, 0.f, 0.f, 0.f);

    for (int base = 0; base < d; base += 8) {
        int cnt = min(8, d - base);
        int src = (lane < cnt) ? csr_src[st + base + lane] : 0;
        int s_i = __shfl_sync(0xffffffffu, src, i);
        float p = (i < cnt) ? __expf(lrelu(as[s_i * 4 + j] + adn)) : 0.f;
        z += p;
#pragma unroll 8
        for (int q = 0; q < cnt; q++) {
            int s = __shfl_sync(0xffffffffu, src, q);
            float pq = __shfl_sync(0xffffffffu, p, q * 4 + myhead);
            uint4 hv = *(const uint4*)(h + (size_t)s * 256 + lane * 8);
            float2 f0 = __half22float2(*(__half2*)&hv.x);
            float2 f1 = __half22float2(*(__half2*)&hv.y);
            float2 f2 = __half22float2(*(__half2*)&hv.z);
            float2 f3 = __half22float2(*(__half2*)&hv.w);
            acc0.x += pq * f0.x; acc0.y += pq * f0.y;
            acc0.z += pq * f1.x; acc0.w += pq * f1.y;
            acc1.x += pq * f2.x; acc1.y += pq * f2.y;
            acc1.z += pq * f3.x; acc1.w += pq * f3.y;
        }
    }
#pragma unroll
    for (int o = 4; o < 32; o <<= 1) z += __shfl_xor_sync(0xffffffffu, z, o);
    float z_my = __shfl_sync(0xffffffffu, z, myhead * 5);
    float rz = 1.f / (z_my + 1e-16f);
    const float4* bp = (const float4*)(bias + lane * 8);
    float4 b0 = bp[0], b1 = bp[1];
    // relu'd node output, 8 channels in this lane
    float v0 = fmaxf(acc0.x * rz + b0.x, 0.f);
    float v1 = fmaxf(acc0.y * rz + b0.y, 0.f);
    float v2 = fmaxf(acc0.z * rz + b0.z, 0.f);
    float v3 = fmaxf(acc0.w * rz + b0.w, 0.f);
    float v4 = fmaxf(acc1.x * rz + b1.x, 0.f);
    float v5 = fmaxf(acc1.y * rz + b1.y, 0.f);
    float v6 = fmaxf(acc1.z * rz + b1.z, 0.f);
    float v7 = fmaxf(acc1.w * rz + b1.w, 0.f);

    // fused layer-3 GEMM: h3 = relu(out) @ W3 [256,2]; W3 rows for channels lane*8..lane*8+7
    const float4* w4 = (const float4*)(W3 + lane * 16);
    float4 wa = w4[0], wb = w4[1], wc = w4[2], wd = w4[3];
    float a0 = v0 * wa.x + v1 * wa.z + v2 * wb.x + v3 * wb.z +
               v4 * wc.x + v5 * wc.z + v6 * wd.x + v7 * wd.z;
    float a1 = v0 * wa.y + v1 * wa.w + v2 * wb.y + v3 * wb.w +
               v4 * wc.y + v5 * wc.w + v6 * wd.y + v7 * wd.w;
#pragma unroll
    for (int o = 16; o; o >>= 1) {
        a0 += __shfl_xor_sync(0xffffffffu, a0, o);
        a1 += __shfl_xor_sync(0xffffffffu, a1, o);
    }
    if (lane == 0) {
        h3_out[2 * node] = a0;
        h3_out[2 * node + 1] = a1;
        as3_out[node] = a0 * __ldg(&a_s3[0]) + a1 * __ldg(&a_s3[1]);
        ad3_out[node] = a0 * __ldg(&a_d3[0]) + a1 * __ldg(&a_d3[1]);
    }
}

// ---------------- layer3 aggregation, no-max softmax (H=1, C=2) ----------------
__global__ void agg3_fused_kernel(const float* __restrict__ h3, const int* __restrict__ csr_src,
                                  const int* __restrict__ offs, const int* __restrict__ deg,
                                  const float* __restrict__ as, const float* __restrict__ ad,
                                  const float* __restrict__ bias, float* __restrict__ out, int n) {
    int i = blockIdx.x * blockDim.x + threadIdx.x;
    if (i >= n) return;
    int st = offs[i], d = deg[i];
    float adn = ad[i];
    float zt = 0.f;
    float a0 = 0.f, a1 = 0.f;
    for (int k = 0; k < d; k++) {
        int s = csr_src[st + k];
        float p = __expf(lrelu(as[s] + adn));
        zt += p;
        a0 += p * h3[2 * s];
        a1 += p * h3[2 * s + 1];
    }
    float rz = 1.f / (zt + 1e-16f);
    out[2 * i] = a0 * rz + bias[0];
    out[2 * i + 1] = a1 * rz + bias[1];
}

// ---------------- launcher ----------------
extern "C" void kernel_launch(void* const* d_in, const int* in_sizes, int n_in,
                              void* d_out, int out_size) {
    const float* x   = (const float*)d_in[0];
    const int*   ei  = (const int*)d_in[1];
    const float* W1  = (const float*)d_in[2];
    const float* as1 = (const float*)d_in[3];
    const float* ad1 = (const float*)d_in[4];
    const float* b1  = (const float*)d_in[5];
    const float* W2  = (const float*)d_in[6];
    const float* as2 = (const float*)d_in[7];
    const float* ad2 = (const float*)d_in[8];
    const float* b2  = (const float*)d_in[9];
    const float* W3  = (const float*)d_in[10];
    const float* as3 = (const float*)d_in[11];
    const float* ad3 = (const float*)d_in[12];
    const float* b3  = (const float*)d_in[13];
    float* outp = (float*)d_out;

    int n = in_sizes[0] / 128;
    int E = in_sizes[1] / 2;

    __half *hbuf, *aggbuf, *xh, *w1h, *w2h;
    float *h3, *as, *ad, *as3b, *ad3b;
    int *deg, *offs, *cursor, *bsum, *csr_src;
    cudaGetSymbolAddress((void**)&hbuf, g_hbuf);
    cudaGetSymbolAddress((void**)&aggbuf, g_aggbuf);
    cudaGetSymbolAddress((void**)&xh, g_xh);
    cudaGetSymbolAddress((void**)&w1h, g_w1h);
    cudaGetSymbolAddress((void**)&w2h, g_w2h);
    cudaGetSymbolAddress((void**)&h3, g_h3);
    cudaGetSymbolAddress((void**)&as, g_as);
    cudaGetSymbolAddress((void**)&ad, g_ad);
    cudaGetSymbolAddress((void**)&as3b, g_as3);
    cudaGetSymbolAddress((void**)&ad3b, g_ad3);
    cudaGetSymbolAddress((void**)&deg, g_deg);
    cudaGetSymbolAddress((void**)&offs, g_offs);
    cudaGetSymbolAddress((void**)&cursor, g_cursor);
    cudaGetSymbolAddress((void**)&bsum, g_bsum);
    cudaGetSymbolAddress((void**)&csr_src, g_csr_src);

    cudaFuncSetAttribute(mma_gemm_kernel, cudaFuncAttributeMaxDynamicSharedMemorySize, GEMM_SMEM);

    int nb = cdiv(n, 256);
    dim3 gemm_grid(cdiv(n, 128), 4);
    int agg_blocks = cdiv(n * 32, 256);

    // fork side stream for CSR build (overlap with converts + GEMM1)
    cudaStream_t sB;
    cudaStreamCreateWithFlags(&sB, cudaStreamNonBlocking);
    cudaEvent_t eFork, eJoin;
    cudaEventCreateWithFlags(&eFork, cudaEventDisableTiming);
    cudaEventCreateWithFlags(&eJoin, cudaEventDisableTiming);
    cudaEventRecord(eFork, 0);
    cudaStreamWaitEvent(sB, eFork, 0);

    // main stream: converts + GEMM1
    f32_to_f16_kernel<<<cdiv(n * 128 / 4, 256), 256>>>(x, xh, n * 128 / 4);
    f32_to_f16_kernel<<<cdiv(128 * 256 / 4, 256), 256>>>(W1, w1h, 128 * 256 / 4);
    f32_to_f16_kernel<<<cdiv(256 * 256 / 4, 256), 256>>>(W2, w2h, 256 * 256 / 4);
    mma_gemm_kernel<<<gemm_grid, 256, GEMM_SMEM>>>(xh, w1h, hbuf, as1, ad1, as, ad, n, 128);

    // side stream: CSR build
    fill_i32<<<cdiv(n, 256), 256, 0, sB>>>(deg, 0, n);
    hist_kernel<<<cdiv(E, 256), 256, 0, sB>>>(ei, deg, E);
    scan_block_kernel<<<nb, 256, 0, sB>>>(deg, offs, bsum, n);
    scan_add_kernel<<<nb, 256, 0, sB>>>(offs, cursor, bsum, n, nb);
    scatter_kernel<<<cdiv(E, 256), 256, 0, sB>>>(ei, cursor, csr_src, E);
    cudaEventRecord(eJoin, sB);
    cudaStreamWaitEvent(0, eJoin, 0);

    // Layer 1 aggregation (R12 kernel, unchanged)
    agg_warp_kernel<<<agg_blocks, 256>>>(hbuf, csr_src, offs, deg, as, ad, b1, aggbuf, n, 1);

    // Layer 2 GEMM
    mma_gemm_kernel<<<gemm_grid, 256, GEMM_SMEM>>>(aggbuf, w2h, hbuf, as2, ad2, as, ad, n, 256);

    // Layer 2 aggregation fused with layer-3 GEMM (separate kernel, dedicated buffers)
    agg_warp_final_kernel<<<agg_blocks, 256>>>(hbuf, csr_src, offs, deg, as, ad, b2,
                                               W3, as3, ad3, h3, as3b, ad3b, n);

    // Layer 3 edge phase
    agg3_fused_kernel<<<cdiv(n, 256), 256>>>(h3, csr_src, offs, deg, as3b, ad3b, b3, outp, n);
}